// round 14
// baseline (speedup 1.0000x reference)
#include <cuda_runtime.h>

// RayPointRefiner: inverse-CDF fine sampling + fully-analytic integer merge.
// N_RAYS=524288, N_PTS=64, N_FINE=64, out=[N_RAYS,128] sorted.
//
// One warp per ray; lane l owns cdf intervals A=2l, B=2l+1.
// u_k = k/63 uniform => interval boundaries t_j = ceil(63*cdf_j), computed
// LOCALLY per lane from bit-identical cdf values (c0 of lane l == c2 of lane
// l-1 exactly) => consistent tiling of [0,64) with zero cross-lane fixup.
// Divergent loops scatter the full interpolation quad qk[k] (one STS.128).
// Uniform phase: lane processes samples k=lane, k=lane+32 with a coalesced
// LDS.128 + fma, scattering z straight to its merged position
// k + (m+1) + (k>=kstar); coarse z[i] goes to i + kstar(interval i-1).
// kstar = ceil(63*u*) at the straddled coarse point -> bijective, no sort.

#define EPSF 1e-5f

constexpr int N_RAYS  = 524288;
constexpr int WPB     = 8;
constexpr int THREADS = WPB * 32;
constexpr unsigned FULL = 0xffffffffu;
constexpr float INV63 = 1.0f / 63.0f;

__global__ __launch_bounds__(THREADS) void refine_kernel(
    const float* __restrict__ lengths,
    const float* __restrict__ rw,
    float* __restrict__ out_g)
{
    __shared__ __align__(16) float4 qk_sh[WPB][64];
    __shared__ __align__(16) float  o_sh [WPB][128];
    const int lane = threadIdx.x & 31;
    const int warp = threadIdx.x >> 5;
    const int ray  = blockIdx.x * WPB + warp;
    float4* qk = qk_sh[warp];
    float*  o  = o_sh[warp];

    // ---- coalesced loads: lane l gets elements 2l, 2l+1 ----
    const float2 za = ((const float2*)lengths)[(size_t)ray * 32 + lane];
    const float2 wa = ((const float2*)rw)     [(size_t)ray * 32 + lane];

    const float znext = __shfl_down_sync(FULL, za.x, 1);   // z[2l+2]
    const float wnext = __shfl_down_sync(FULL, wa.x, 1);   // rw[2l+2]

    const float bin0 = 0.5f * (za.x + za.y);               // bins[2l]
    float       bin1 = 0.5f * (za.y + znext);              // bins[2l+1]
    float       binN = __shfl_down_sync(FULL, bin0, 1);    // bins[2l+2]

    // weights w[2l]=rw[2l+1]+eps, w[2l+1]=rw[2l+2]+eps (lanes 0..30)
    float w0 = 0.0f, w1 = 0.0f;
    if (lane < 31) { w0 = wa.y + EPSF; w1 = wnext + EPSF; }

    // inclusive warp scan of pair sums
    float incl = w0 + w1;
    #pragma unroll
    for (int d = 1; d < 32; d <<= 1) {
        float v = __shfl_up_sync(FULL, incl, d);
        if (lane >= d) incl += v;
    }
    float excl = __shfl_up_sync(FULL, incl, 1);
    if (lane == 0) excl = 0.0f;
    const float total = __shfl_sync(FULL, incl, 31);
    const float invW  = __fdividef(1.0f, total);

    // cdf boundaries (monotone; adjacent lanes share bit-identical values)
    float c0 = excl * invW;              // cdf[2l]
    float c1 = (excl + w0) * invW;       // cdf[2l+1]
    float c2 = incl * invW;              // cdf[2l+2]
    if (lane == 30) c2 = 1.0f;           // exact top at cdf[62]
    if (lane == 31) { c0 = 1.0f; c1 = 1.0f; c2 = 1.0f; bin1 = bin0; binN = bin0; }

    // local thresholds: t0 bit-identical to neighbor's t2 (same input bits)
    int t0 = min(max((int)ceilf(c0 * 63.0f), 0), 64);
    int t1 = min(max((int)ceilf(c1 * 63.0f), 0), 64);
    int t2 = min(max((int)ceilf(c2 * 63.0f), 0), 64);
    if (lane == 31) { t0 = 63; t1 = 64; t2 = 64; }  // k=63 -> bins[62] exactly
    t1 = min(t1, t2);                                // guard forced lane 30
    t0 = min(t0, t1);

    // kstar: crossing index of straddled coarse point inside each interval
    const float dA = c1 - c0, dbA = bin1 - bin0;
    const float dB = c2 - c1, dbB = binN - bin1;
    const float uA = c0 + (za.y  - bin0) * __fdividef(dA, dbA);
    const float uB = c1 + (znext - bin1) * __fdividef(dB, dbB);
    int ksA = min(max((int)ceilf(uA * 63.0f), t0), t1);
    int ksB = min(max((int)ceilf(uB * 63.0f), t1), t2);
    if (lane == 31) { ksA = 64; ksB = 64; }          // z[63] above everything

    // interpolation quads; Q.w packs (kstar<<8)|(m+1)
    const float rdA = __fdividef(dbA, (dA < EPSF) ? 1.0f : dA);
    const float rdB = __fdividef(dbB, (dB < EPSF) ? 1.0f : dB);
    const float4 QA = make_float4(c0, bin0, rdA,
                                  __int_as_float((ksA << 8) | (2 * lane + 1)));
    const float4 QB = make_float4(c1, bin1, rdB,
                                  __int_as_float((ksB << 8) | (2 * lane + 2)));

    // divergent scatter: one STS.128 per owned sample
    for (int k = t0; k < t1; ++k) qk[k] = QA;
    for (int k = t1; k < t2; ++k) qk[k] = QB;
    __syncwarp();

    // ---- uniform sample phase: coalesced qk loads, k = lane, lane+32 ----
    #pragma unroll
    for (int q = 0; q < 2; ++q) {
        const int k = lane + 32 * q;
        const float4 Q = qk[k];
        const float u = (k == 63) ? 1.0f : (float)k * INV63;
        const float z = fmaf(u - Q.x, Q.z, Q.y);
        const int p   = __float_as_int(Q.w);
        const int pos = k + (p & 255) + (k >= (p >> 8));
        o[pos] = z;
    }

    // ---- coarse placements (closed form) ----
    int pk = __shfl_up_sync(FULL, ksB, 1);           // kstar of interval 2l-1
    if (lane == 0) pk = 0;
    o[2 * lane + pk]      = za.x;                    // z[2l]
    o[2 * lane + 1 + ksA] = za.y;                    // z[2l+1]
    __syncwarp();

    // ---- coalesced float4 store ----
    const float4 r = ((const float4*)o)[lane];
    ((float4*)out_g)[(size_t)ray * 32 + lane] = r;
}

extern "C" void kernel_launch(void* const* d_in, const int* in_sizes, int n_in,
                              void* d_out, int out_size) {
    // metadata order: origins, directions, lengths, xys, ray_weights
    const float* lengths = (const float*)d_in[2];
    const float* weights = (const float*)d_in[4];
    float* out = (float*)d_out;
    refine_kernel<<<N_RAYS / WPB, THREADS>>>(lengths, weights, out);
}

// round 17
// speedup vs baseline: 1.0418x; 1.0418x over previous
#include <cuda_runtime.h>

// RayPointRefiner: inverse-CDF fine sampling + fully-analytic integer merge.
// N_RAYS=524288, N_PTS=64, N_FINE=64, out=[N_RAYS,128] sorted.
//
// One warp per ray; lane l owns cdf intervals A=2l, B=2l+1.
// u_k = k/63 uniform => interval boundaries t_j = ceil(63*cdf_j), computed
// LOCALLY per lane from bit-identical cdf values (c0 of lane l == c2 of lane
// l-1 exactly) => consistent tiling of [0,64) with zero cross-lane fixup.
// ONE divergent loop per lane over k in [t0,t2) computes z directly
// (FADD+FFMA) and scatters it via STS.32 to its final merged position
// k + (m+1) + (k>=kstar); coarse z[i] goes to i + kstar(interval i-1).
// kstar = ceil(63*u*) at the straddled coarse point -> bijective, no sort,
// no staging arrays: shared = 512B output buffer per ray only.

#define EPSF 1e-5f

constexpr int N_RAYS  = 524288;
constexpr int WPB     = 8;
constexpr int THREADS = WPB * 32;
constexpr unsigned FULL = 0xffffffffu;
constexpr float INV63 = 1.0f / 63.0f;

__global__ __launch_bounds__(THREADS) void refine_kernel(
    const float* __restrict__ lengths,
    const float* __restrict__ rw,
    float* __restrict__ out_g)
{
    __shared__ __align__(16) float o_sh[WPB][128];
    const int lane = threadIdx.x & 31;
    const int warp = threadIdx.x >> 5;
    const int ray  = blockIdx.x * WPB + warp;
    float* o = o_sh[warp];

    // ---- coalesced loads: lane l gets elements 2l, 2l+1 ----
    const float2 za = ((const float2*)lengths)[(size_t)ray * 32 + lane];
    const float2 wa = ((const float2*)rw)     [(size_t)ray * 32 + lane];

    const float znext = __shfl_down_sync(FULL, za.x, 1);   // z[2l+2]
    const float wnext = __shfl_down_sync(FULL, wa.x, 1);   // rw[2l+2]

    const float bin0 = 0.5f * (za.x + za.y);               // bins[2l]
    float       bin1 = 0.5f * (za.y + znext);              // bins[2l+1]
    float       binN = __shfl_down_sync(FULL, bin0, 1);    // bins[2l+2]

    // weights w[2l]=rw[2l+1]+eps, w[2l+1]=rw[2l+2]+eps (lanes 0..30)
    float w0 = 0.0f, w1 = 0.0f;
    if (lane < 31) { w0 = wa.y + EPSF; w1 = wnext + EPSF; }

    // inclusive warp scan of pair sums
    float incl = w0 + w1;
    #pragma unroll
    for (int d = 1; d < 32; d <<= 1) {
        float v = __shfl_up_sync(FULL, incl, d);
        if (lane >= d) incl += v;
    }
    float excl = __shfl_up_sync(FULL, incl, 1);
    if (lane == 0) excl = 0.0f;
    const float total = __shfl_sync(FULL, incl, 31);
    const float invW  = __fdividef(1.0f, total);

    // cdf boundaries (monotone; adjacent lanes share bit-identical values)
    float c0 = excl * invW;              // cdf[2l]
    float c1 = (excl + w0) * invW;       // cdf[2l+1]
    float c2 = incl * invW;              // cdf[2l+2]
    if (lane == 30) c2 = 1.0f;           // exact top at cdf[62]
    if (lane == 31) { c0 = 1.0f; c1 = 1.0f; c2 = 1.0f; bin1 = bin0; binN = bin0; }

    // local thresholds: t0 bit-identical to neighbor's t2 (same input bits)
    int t0 = min(max((int)ceilf(c0 * 63.0f), 0), 64);
    int t1 = min(max((int)ceilf(c1 * 63.0f), 0), 64);
    int t2 = min(max((int)ceilf(c2 * 63.0f), 0), 64);
    if (lane == 31) { t0 = 63; t1 = 64; t2 = 64; }  // k=63 -> bins[62] exactly
    t1 = min(t1, t2);                                // guard forced lane 30
    t0 = min(t0, t1);

    // kstar: crossing index of straddled coarse point inside each interval
    const float dA = c1 - c0, dbA = bin1 - bin0;
    const float dB = c2 - c1, dbB = binN - bin1;
    const float uA = c0 + (za.y  - bin0) * __fdividef(dA, dbA);
    const float uB = c1 + (znext - bin1) * __fdividef(dB, dbB);
    int ksA = min(max((int)ceilf(uA * 63.0f), t0), t1);
    int ksB = min(max((int)ceilf(uB * 63.0f), t1), t2);
    if (lane == 31) { ksA = 64; ksB = 64; }          // z[63] above everything

    // interpolation slopes (reference denom<eps guard folded in)
    const float rdA = __fdividef(dbA, (dA < EPSF) ? 1.0f : dA);
    const float rdB = __fdividef(dbB, (dB < EPSF) ? 1.0f : dB);

    // ---- single divergent loop: compute + scatter final samples ----
    // k in [t0,t1): interval A (base 2l+1); k in [t1,t2): interval B (base 2l+2)
    // For lane 31 (k=63): rdA==0 -> z = bin0 = bins[62] regardless of u.
    float u = (float)t0 * INV63;
    for (int k = t0; k < t2; ++k, u += INV63) {
        const bool inA = (k < t1);
        const float c   = inA ? c0   : c1;
        const float rd  = inA ? rdA  : rdB;
        const float bn  = inA ? bin0 : bin1;
        const int   ks  = inA ? ksA  : ksB;
        const int   mp1 = 2 * lane + (inA ? 1 : 2);
        const float z = fmaf(u - c, rd, bn);
        o[k + mp1 + (k >= ks)] = z;
    }

    // ---- coarse placements (closed form) ----
    int pk = __shfl_up_sync(FULL, ksB, 1);           // kstar of interval 2l-1
    if (lane == 0) pk = 0;
    o[2 * lane + pk]      = za.x;                    // z[2l]
    o[2 * lane + 1 + ksA] = za.y;                    // z[2l+1]
    __syncwarp();

    // ---- coalesced float4 store ----
    const float4 r = ((const float4*)o)[lane];
    ((float4*)out_g)[(size_t)ray * 32 + lane] = r;
}

extern "C" void kernel_launch(void* const* d_in, const int* in_sizes, int n_in,
                              void* d_out, int out_size) {
    // metadata order: origins, directions, lengths, xys, ray_weights
    const float* lengths = (const float*)d_in[2];
    const float* weights = (const float*)d_in[4];
    float* out = (float*)d_out;
    refine_kernel<<<N_RAYS / WPB, THREADS>>>(lengths, weights, out);
}